// round 8
// baseline (speedup 1.0000x reference)
#include <cuda_runtime.h>

// LFQ: z [4,14,32,32] f32. Codebook = all +-1 bit patterns -> T=0.01 softmax
// factorizes per bit. With em = expf(-400|z_d|): pc=1/(1+em), po=em*pc, flip
// ratio po/pc = em exactly. A bit is "soft" only when em > 0 in fp32, so a
// token has only 2^nsoft (~8) nonzero codes -> enumerate and scatter into a
// u64 fixed-point histogram (integer atomics commute => bit-deterministic).
//
// Single persistent kernel, 148 blocks x 128 thr (1 CTA/SM). Phase 1 is
// balanced: warp 0 of blocks 0..127 = token work (1 token-warp per SM);
// warps 1..3 of ALL blocks = ring-buffer marking. Token idx bits and marking
// bits share the block's smem bitset, flushed once.
//
// Output (f32): quantized[57344], commit, entropy_loss, usage, idx_flat[4096].

#define N_TOK 4096
#define DIM   14
#define HW    1024
#define NE    16384
#define QELEMS (N_TOK * DIM)       // 57344
#define FIXSCALE 1099511627776.0   // 2^40
#define FULLM 0xffffffffu
#define NBLK 148
#define NTHR 128
#define NMARK (NBLK * 96)          // 14208 marking threads

__device__ unsigned long long g_hist[NE];
__device__ unsigned int       g_bitset[2048];
__device__ float              g_wcom[128];
__device__ float              g_went[128];
__device__ float              g_sae[NBLK];
__device__ float              g_scom[NBLK];
__device__ float              g_sent[NBLK];
__device__ int                g_scnt[NBLK];
__device__ unsigned int       g_bar0, g_bar1, g_ticket;

// ---------------------------------------------------------------------------
__device__ __forceinline__ void grid_barrier(unsigned int* bar) {
    __syncthreads();
    if (threadIdx.x == 0) {
        __threadfence();
        atomicAdd(bar, 1u);
        while (*(volatile unsigned int*)bar < (unsigned)NBLK) { }
    }
    __syncthreads();
    __threadfence();
}

__device__ __forceinline__ void emit_subsets_strided(
    unsigned m, float pbase, unsigned idx, const float* __restrict__ ratio,
    unsigned start, unsigned stride)
{
    unsigned total = 1u << __popc(m);
    for (unsigned s = start; s < total; s += stride) {
        float p = pbase;
        unsigned code = idx;
        unsigned sb = s;
        #pragma unroll
        for (int d = 0; d < DIM; d++) {
            if ((m >> d) & 1u) {
                if (sb & 1u) { p *= ratio[d]; code ^= (1u << d); }
                sb >>= 1u;
            }
        }
        unsigned long long f = __double2ull_rn((double)p * FIXSCALE);
        if (f) atomicAdd(&g_hist[code], f);
    }
}

// ---------------------------------------------------------------------------
__global__ void __launch_bounds__(NTHR, 1)
k_all(const float* __restrict__ z, const int* __restrict__ used,
      float* __restrict__ out) {
    int blk = blockIdx.x;
    int tid = threadIdx.x;
    int gt  = blk * NTHR + tid;

    __shared__ unsigned s_bs[2048];
    __shared__ float reda[NTHR], redc[NTHR], rede[NTHR];
    __shared__ int   redn[NTHR];

    // ---- phase 0: zero global scratch + block's smem bitset --------------
    if (gt < NE)   g_hist[gt]   = 0ull;
    if (gt < 2048) g_bitset[gt] = 0u;
    for (int i = tid; i < 2048; i += NTHR) s_bs[i] = 0u;

    grid_barrier(&g_bar0);     // also orders s_bs zeroing (has __syncthreads)

    // ---- phase 1: token work (warp 0, blocks<128) || marking (warps 1-3) --
    if (tid < 32) {
        if (blk < 128) {
            int lane = tid;
            int t  = blk * 32 + lane;          // token id
            int b  = t >> 10;
            int hw = t & 1023;
            const float* zp = z   + b * (DIM * HW) + hw;
            float*       qp = out + b * (DIM * HW) + hw;

            float com = 0.f, ent = 0.f, pbase = 1.f;
            unsigned idx = 0u, mask = 0u;
            float ratio[DIM];

            #pragma unroll
            for (int d = 0; d < DIM; d++) {
                float zv = zp[d * HW];
                float q  = (zv > 0.f) ? 1.f : -1.f;
                qp[d * HW] = q;
                float df = zv - q;
                com += df * df;
                if (zv > 0.f) idx |= (1u << d);

                float ax = 400.f * fabsf(zv);
                float em = expf(-ax);          // == flip ratio
                float pc = 1.f / (1.f + em);
                float po = em * pc;
                pbase *= pc;
                ratio[d] = em;
                if (po > 0.f) mask |= (1u << d);

                ent += log1pf(em) + po * ax;
            }

            out[QELEMS + 3 + t] = (float)idx;
            atomicOr(&s_bs[idx >> 5], 1u << (idx & 31u));   // smem, merged later

            #pragma unroll
            for (int o = 16; o; o >>= 1) {
                com += __shfl_down_sync(FULLM, com, o);
                ent += __shfl_down_sync(FULLM, ent, o);
            }
            if (lane == 0) { g_wcom[blk] = com; g_went[blk] = ent; }

            unsigned nsoft = __popc(mask);
            if (nsoft < 6)
                emit_subsets_strided(mask, pbase, idx, ratio, 0u, 1u);

            unsigned heavy = __ballot_sync(FULLM, nsoft >= 6);
            while (heavy) {
                int L = __ffs(heavy) - 1;
                heavy &= heavy - 1u;
                unsigned hm   = __shfl_sync(FULLM, mask,  L);
                float    hp   = __shfl_sync(FULLM, pbase, L);
                unsigned hidx = __shfl_sync(FULLM, idx,   L);
                float hr[DIM];
                #pragma unroll
                for (int d = 0; d < DIM; d++) hr[d] = __shfl_sync(FULLM, ratio[d], L);
                emit_subsets_strided(hm, hp, hidx, hr, (unsigned)lane, 32u);
            }
        }
    } else {
        // marking: used[4096:65536) = 61440 entries over 14208 threads
        int m = blk * 96 + (tid - 32);
        unsigned curw = 0xffffffffu, curm = 0u;
        for (int k = m; k < 65536 - N_TOK; k += NMARK) {
            unsigned v = ((unsigned)used[N_TOK + k]) & 65535u;
            unsigned w = v >> 5, mm = 1u << (v & 31u);
            if (w == curw) curm |= mm;
            else {
                if (curw != 0xffffffffu) atomicOr(&s_bs[curw], curm);
                curw = w; curm = mm;
            }
        }
        if (curw != 0xffffffffu) atomicOr(&s_bs[curw], curm);
    }
    __syncthreads();

    // flush block bitset (token idx bits + marking bits) to global
    for (int i = tid; i < 2048; i += NTHR) {
        unsigned v = s_bs[i];
        if (v) atomicOr(&g_bitset[i], v);
    }

    grid_barrier(&g_bar1);

    // ---- phase 2: reduce --------------------------------------------------
    float ae = 0.f;
    if (gt < NE) {
        unsigned long long hv = g_hist[gt];
        if (hv) {
            float avg = (float)((double)hv * (1.0 / FIXSCALE) * (1.0 / 4096.0));
            ae = -avg * logf(avg + 1e-5f);
        }
    }
    int   cnt = (gt < 2048) ? __popc(g_bitset[gt]) : 0;
    float cs  = (gt < 128) ? g_wcom[gt] : 0.f;
    float es  = (gt >= 128 && gt < 256) ? g_went[gt - 128] : 0.f;

    reda[tid] = ae; redn[tid] = cnt; redc[tid] = cs; rede[tid] = es;
    __syncthreads();
    for (int o = 64; o; o >>= 1) {
        if (tid < o) {
            reda[tid] += reda[tid + o];
            redn[tid] += redn[tid + o];
            redc[tid] += redc[tid + o];
            rede[tid] += rede[tid + o];
        }
        __syncthreads();
    }
    if (tid == 0) {
        g_sae[blk]  = reda[0];
        g_scnt[blk] = redn[0];
        g_scom[blk] = redc[0];
        g_sent[blk] = rede[0];
    }

    __shared__ int s_last;
    __threadfence();
    if (tid == 0) s_last = (atomicAdd(&g_ticket, 1u) == (unsigned)(NBLK - 1));
    __syncthreads();

    if (s_last) {
        __threadfence();
        float a = 0.f, c2 = 0.f, e2 = 0.f;
        int   c = 0;
        if (tid < NBLK) { a = g_sae[tid]; c = g_scnt[tid]; c2 = g_scom[tid]; e2 = g_sent[tid]; }
        if (tid + NTHR < NBLK) {
            a  += g_sae[tid + NTHR];  c  += g_scnt[tid + NTHR];
            c2 += g_scom[tid + NTHR]; e2 += g_sent[tid + NTHR];
        }
        reda[tid] = a; redn[tid] = c; redc[tid] = c2; rede[tid] = e2;
        __syncthreads();
        for (int o = 64; o; o >>= 1) {
            if (tid < o) {
                reda[tid] += reda[tid + o];
                redn[tid] += redn[tid + o];
                redc[tid] += redc[tid + o];
                rede[tid] += rede[tid + o];
            }
            __syncthreads();
        }
        if (tid == 0) {
            float commit   = 0.25f * redc[0] / (float)QELEMS;
            float sample_e = rede[0] / (float)N_TOK;
            out[QELEMS + 0] = commit;
            out[QELEMS + 1] = 0.1f * (sample_e - reda[0]);
            out[QELEMS + 2] = (float)redn[0] / (float)NE;
            *(volatile unsigned int*)&g_bar0   = 0u;
            *(volatile unsigned int*)&g_bar1   = 0u;
            *(volatile unsigned int*)&g_ticket = 0u;
        }
    }
}

// ---------------------------------------------------------------------------
extern "C" void kernel_launch(void* const* d_in, const int* in_sizes, int n_in,
                              void* d_out, int out_size) {
    const float* z    = (const float*)d_in[0];
    const int*   used = (const int*)d_in[2];
    float*       out  = (float*)d_out;

    k_all<<<NBLK, NTHR>>>(z, used, out);
}

// round 9
// speedup vs baseline: 1.1238x; 1.1238x over previous
#include <cuda_runtime.h>

// LFQ: z [4,14,32,32] f32. Codebook = all +-1 bit patterns -> T=0.01 softmax
// factorizes per bit. With em = expf(-400|z_d|): pc=1/(1+em), po=em*pc, flip
// ratio po/pc = em exactly. A bit is "soft" only when em > 0 in fp32, so a
// token has only 2^nsoft (~8) nonzero codes -> enumerate and scatter into a
// u64 fixed-point histogram (integer atomics commute => bit-deterministic).
//
// Two-node graph: k_main (tokens + ring marking) -> k_reduce (entropy,
// popcount, scalars). k_reduce SELF-CLEANS all scratch (hist, bitset,
// accumulators, ticket) so no memset node is needed: device globals are
// zero-initialized at load and every replay restores the zeroed state.
//
// Output (f32): quantized[57344], commit, entropy_loss, usage, idx_flat[4096].

#define N_TOK 4096
#define DIM   14
#define HW    1024
#define NE    16384
#define QELEMS (N_TOK * DIM)       // 57344
#define FIXSCALE 1099511627776.0   // 2^40
#define FULLM 0xffffffffu

__device__ unsigned long long g_hist[NE];     // zeroed by k_reduce each replay
__device__ unsigned int       g_bitset[2048]; // zeroed by k_reduce each replay
__device__ float              g_wcom[128];    // every slot rewritten each replay
__device__ float              g_went[128];
__device__ long long          g_acc[3];       // fixed-point ae, commit, ent
__device__ int                g_cnt;          // usage popcount accumulator
__device__ unsigned int       g_ticket;

// ---------------------------------------------------------------------------
__device__ __forceinline__ void emit_subsets_strided(
    unsigned m, float pbase, unsigned idx, const float* __restrict__ ratio,
    unsigned start, unsigned stride)
{
    unsigned total = 1u << __popc(m);
    for (unsigned s = start; s < total; s += stride) {
        float p = pbase;
        unsigned code = idx;
        unsigned sb = s;
        #pragma unroll
        for (int d = 0; d < DIM; d++) {
            if ((m >> d) & 1u) {
                if (sb & 1u) { p *= ratio[d]; code ^= (1u << d); }
                sb >>= 1u;
            }
        }
        unsigned long long f = __double2ull_rn((double)p * FIXSCALE);
        if (f) atomicAdd(&g_hist[code], f);
    }
}

// Blocks 0..63: token work (2 warps, thread = token).
// Blocks 64..223: ring-buffer leftover marking (384 entries each).
__global__ void k_main(const float* __restrict__ z, const int* __restrict__ used,
                       float* __restrict__ out) {
    int blk = blockIdx.x;
    int tid = threadIdx.x;                 // 64 threads

    if (blk < 64) {
        int lane = tid & 31;
        int wg = blk * 2 + (tid >> 5);     // global warp id 0..127
        int t  = wg * 32 + lane;
        int b  = t >> 10;
        int hw = t & 1023;
        const float* zp = z   + b * (DIM * HW) + hw;
        float*       qp = out + b * (DIM * HW) + hw;

        float com = 0.f, ent = 0.f, pbase = 1.f;
        unsigned idx = 0u, mask = 0u;
        float ratio[DIM];

        #pragma unroll
        for (int d = 0; d < DIM; d++) {
            float zv = zp[d * HW];
            float q  = (zv > 0.f) ? 1.f : -1.f;
            qp[d * HW] = q;
            float df = zv - q;
            com += df * df;
            if (zv > 0.f) idx |= (1u << d);

            float ax = 400.f * fabsf(zv);
            float em = expf(-ax);              // == flip ratio
            float pc = 1.f / (1.f + em);
            float po = em * pc;
            pbase *= pc;
            ratio[d] = em;
            if (po > 0.f) mask |= (1u << d);

            ent += log1pf(em) + po * ax;
        }

        out[QELEMS + 3 + t] = (float)idx;
        atomicOr(&g_bitset[idx >> 5], 1u << (idx & 31u));

        #pragma unroll
        for (int o = 16; o; o >>= 1) {
            com += __shfl_down_sync(FULLM, com, o);
            ent += __shfl_down_sync(FULLM, ent, o);
        }
        if (lane == 0) { g_wcom[wg] = com; g_went[wg] = ent; }

        unsigned nsoft = __popc(mask);
        if (nsoft < 6)
            emit_subsets_strided(mask, pbase, idx, ratio, 0u, 1u);

        unsigned heavy = __ballot_sync(FULLM, nsoft >= 6);
        while (heavy) {
            int L = __ffs(heavy) - 1;
            heavy &= heavy - 1u;
            unsigned hm   = __shfl_sync(FULLM, mask,  L);
            float    hp   = __shfl_sync(FULLM, pbase, L);
            unsigned hidx = __shfl_sync(FULLM, idx,   L);
            float hr[DIM];
            #pragma unroll
            for (int d = 0; d < DIM; d++) hr[d] = __shfl_sync(FULLM, ratio[d], L);
            emit_subsets_strided(hm, hp, hidx, hr, (unsigned)lane, 32u);
        }
    } else {
        // marking: used[4096:65536) = 61440 entries, 160 blocks x 384
        __shared__ unsigned s_bs[2048];
        for (int i = tid; i < 2048; i += 64) s_bs[i] = 0u;
        __syncthreads();

        const int* src = used + N_TOK + (blk - 64) * 384;
        unsigned curw = 0xffffffffu, curm = 0u;
        #pragma unroll
        for (int it = 0; it < 6; it++) {
            unsigned v = ((unsigned)src[tid + it * 64]) & 65535u;
            unsigned w = v >> 5, mm = 1u << (v & 31u);
            if (w == curw) curm |= mm;
            else {
                if (curw != 0xffffffffu) atomicOr(&s_bs[curw], curm);
                curw = w; curm = mm;
            }
        }
        if (curw != 0xffffffffu) atomicOr(&s_bs[curw], curm);
        __syncthreads();

        for (int i = tid; i < 2048; i += 64) {
            unsigned v = s_bs[i];
            if (v) atomicOr(&g_bitset[i], v);
        }
    }
}

// ---------------------------------------------------------------------------
// 64 blocks x 256 threads. Block g: codes [g*256,(g+1)*256) entropy + zero,
// 32 bitset words popcount + zero; block 0 folds commit/ent partials.
// Block partials (fixed-order tree) -> fixed-point integer atomics (commute
// => deterministic). Ticket-elected last block writes scalars + resets state.
__global__ void k_reduce(float* __restrict__ out) {
    __shared__ float reda[256], redc[256], rede[256];
    __shared__ int   redn[256];
    int tid = threadIdx.x;
    int g   = blockIdx.x;

    int j = g * 256 + tid;
    unsigned long long hv = g_hist[j];
    if (hv) g_hist[j] = 0ull;              // self-clean for next replay
    float ae = 0.f;
    if (hv) {
        float avg = (float)((double)hv * (1.0 / FIXSCALE) * (1.0 / 4096.0));
        ae = -avg * logf(avg + 1e-5f);
    }

    int cnt = 0;
    if (tid < 32) {
        unsigned w = g_bitset[g * 32 + tid];
        if (w) g_bitset[g * 32 + tid] = 0u;
        cnt = __popc(w);
    }

    float cs = 0.f, es = 0.f;
    if (g == 0) {
        if (tid < 128) cs = g_wcom[tid];
        else           es = g_went[tid - 128];
    }

    reda[tid] = ae; redn[tid] = cnt; redc[tid] = cs; rede[tid] = es;
    __syncthreads();
    for (int o = 128; o; o >>= 1) {
        if (tid < o) {
            reda[tid] += reda[tid + o];
            redn[tid] += redn[tid + o];
            redc[tid] += redc[tid + o];
            rede[tid] += rede[tid + o];
        }
        __syncthreads();
    }
    if (tid == 0) {
        atomicAdd((unsigned long long*)&g_acc[0],
                  (unsigned long long)__double2ll_rn((double)reda[0] * FIXSCALE));
        atomicAdd(&g_cnt, redn[0]);
        if (g == 0) {
            atomicAdd((unsigned long long*)&g_acc[1],
                      (unsigned long long)__double2ll_rn((double)redc[0] * FIXSCALE));
            atomicAdd((unsigned long long*)&g_acc[2],
                      (unsigned long long)__double2ll_rn((double)rede[0] * FIXSCALE));
        }
    }

    __shared__ int s_last;
    __threadfence();
    if (tid == 0) s_last = (atomicAdd(&g_ticket, 1u) == 63u);
    __syncthreads();

    if (s_last && tid == 0) {
        __threadfence();
        long long a0 = *(volatile long long*)&g_acc[0];
        long long a1 = *(volatile long long*)&g_acc[1];
        long long a2 = *(volatile long long*)&g_acc[2];
        int       uc = *(volatile int*)&g_cnt;
        float avg_e    = (float)((double)a0 * (1.0 / FIXSCALE));
        float commit   = 0.25f * (float)((double)a1 * (1.0 / FIXSCALE)) / (float)QELEMS;
        float sample_e = (float)((double)a2 * (1.0 / FIXSCALE)) / (float)N_TOK;
        out[QELEMS + 0] = commit;
        out[QELEMS + 1] = 0.1f * (sample_e - avg_e);
        out[QELEMS + 2] = (float)uc / (float)NE;
        // reset for next replay
        *(volatile long long*)&g_acc[0] = 0ll;
        *(volatile long long*)&g_acc[1] = 0ll;
        *(volatile long long*)&g_acc[2] = 0ll;
        *(volatile int*)&g_cnt          = 0;
        *(volatile unsigned int*)&g_ticket = 0u;
    }
}

// ---------------------------------------------------------------------------
extern "C" void kernel_launch(void* const* d_in, const int* in_sizes, int n_in,
                              void* d_out, int out_size) {
    const float* z    = (const float*)d_in[0];
    const int*   used = (const int*)d_in[2];
    float*       out  = (float*)d_out;

    k_main<<<224, 64>>>(z, used, out);
    k_reduce<<<64, 256>>>(out);
}

// round 11
// speedup vs baseline: 1.9959x; 1.7759x over previous
#include <cuda_runtime.h>

// LFQ: z [4,14,32,32] f32. Codebook = all +-1 bit patterns -> T=0.01 softmax
// factorizes per bit. With em = expf(-400|z_d|): pc = 1/(1+em), po = em*pc,
// flip ratio po/pc = em. pbase = prod(pc) = 1/prod(1+em) (ONE divide);
// sum log1p(em) = logf(prod(1+em)) (ONE log). A soft bit contributes a
// nonzero fixed-point emission only if em >= 2^-41 (else every subset's
// p < 2^-41 and rn(p*2^40)=0) -> prune exactly; remaining ~2 subsets/token
// scatter into a u64 fixed-point histogram (integer atomics commute =>
// bit-deterministic).
//
// Output (f32): quantized[57344], commit, entropy_loss, usage, idx_flat[4096].

#define N_TOK 4096
#define DIM   14
#define HW    1024
#define NE    16384
#define QELEMS (N_TOK * DIM)       // 57344
#define FIXSCALE 1099511627776.0   // 2^40
#define FULLM 0xffffffffu
#define EM_MIN 4.5474735088646412e-13f   // 2^-41

__device__ unsigned long long g_hist[NE];     // self-cleaned by k_reduce
__device__ unsigned int       g_bitset[2048]; // self-cleaned by k_reduce
__device__ float              g_wcom[128];    // rewritten every replay
__device__ float              g_went[128];
__device__ float              g_pae[64];      // per-block entropy partials
__device__ int                g_pcnt[64];
__device__ float              g_pcs, g_pes;
__device__ unsigned int       g_ticket;       // reset by ticket block

// ---------------------------------------------------------------------------
__device__ __forceinline__ void emit_subsets_strided(
    unsigned m, float pbase, unsigned idx, const float* __restrict__ ratio,
    unsigned start, unsigned stride)
{
    unsigned total = 1u << __popc(m);
    for (unsigned s = start; s < total; s += stride) {
        float p = pbase;
        unsigned code = idx;
        unsigned sb = s;
        #pragma unroll
        for (int d = 0; d < DIM; d++) {
            if ((m >> d) & 1u) {
                if (sb & 1u) { p *= ratio[d]; code ^= (1u << d); }
                sb >>= 1u;
            }
        }
        unsigned long long f = __double2ull_rn((double)p * FIXSCALE);
        if (f) atomicAdd(&g_hist[code], f);
    }
}

// Blocks 0..127: one token-warp each (32 tokens). Blocks 128..367: marking.
__global__ void __launch_bounds__(32)
k_main(const float* __restrict__ z, const int* __restrict__ used,
       float* __restrict__ out) {
    int blk = blockIdx.x;
    int tid = threadIdx.x;                 // 32 threads

    if (blk < 128) {
        int t  = blk * 32 + tid;           // token id
        int b  = t >> 10;
        int hw = t & 1023;
        const float* zp = z   + b * (DIM * HW) + hw;
        float*       qp = out + b * (DIM * HW) + hw;

        float com = 0.f, ent2 = 0.f, denom = 1.f;
        unsigned idx = 0u, mask = 0u;
        float ratio[DIM];

        #pragma unroll
        for (int d = 0; d < DIM; d++) {
            float zv = zp[d * HW];
            float q  = (zv > 0.f) ? 1.f : -1.f;
            qp[d * HW] = q;
            float df = zv - q;
            com += df * df;
            if (zv > 0.f) idx |= (1u << d);

            float ax = 400.f * fabsf(zv);
            float em = __expf(-ax);            // flip ratio po/pc
            ratio[d] = em;
            float op = 1.f + em;
            denom *= op;
            if (em >= EM_MIN) mask |= (1u << d);
            // exact per-bit entropy: log1p(em) folded into logf(denom) below
            ent2 = fmaf(ax, __fdividef(em, op), ent2);
        }
        float pbase = __fdividef(1.f, denom);
        float ent   = __logf(denom) + ent2;

        out[QELEMS + 3 + t] = (float)idx;
        atomicOr(&g_bitset[idx >> 5], 1u << (idx & 31u));

        #pragma unroll
        for (int o = 16; o; o >>= 1) {
            com += __shfl_down_sync(FULLM, com, o);
            ent += __shfl_down_sync(FULLM, ent, o);
        }
        if (tid == 0) { g_wcom[blk] = com; g_went[blk] = ent; }

        unsigned nsoft = __popc(mask);
        if (nsoft < 5)
            emit_subsets_strided(mask, pbase, idx, ratio, 0u, 1u);

        unsigned heavy = __ballot_sync(FULLM, nsoft >= 5);
        while (heavy) {
            int L = __ffs(heavy) - 1;
            heavy &= heavy - 1u;
            unsigned hm   = __shfl_sync(FULLM, mask,  L);
            float    hp   = __shfl_sync(FULLM, pbase, L);
            unsigned hidx = __shfl_sync(FULLM, idx,   L);
            float hr[DIM];
            #pragma unroll
            for (int d = 0; d < DIM; d++) hr[d] = __shfl_sync(FULLM, ratio[d], L);
            emit_subsets_strided(hm, hp, hidx, hr, (unsigned)tid, 32u);
        }
    } else {
        // marking: used[4096:65536) = 61440 entries, 240 blocks x 32 thr x 8
        __shared__ unsigned s_bs[2048];
        for (int i = tid; i < 2048; i += 32) s_bs[i] = 0u;
        __syncthreads();

        int m = (blk - 128) * 32 + tid;
        unsigned curw = 0xffffffffu, curm = 0u;
        #pragma unroll
        for (int it = 0; it < 8; it++) {
            unsigned v = ((unsigned)used[N_TOK + m + it * 7680]) & 65535u;
            unsigned w = v >> 5, mm = 1u << (v & 31u);
            if (w == curw) curm |= mm;
            else {
                if (curw != 0xffffffffu) atomicOr(&s_bs[curw], curm);
                curw = w; curm = mm;
            }
        }
        if (curw != 0xffffffffu) atomicOr(&s_bs[curw], curm);
        __syncthreads();

        for (int i = tid; i < 2048; i += 32) {
            unsigned v = s_bs[i];
            if (v) atomicOr(&g_bitset[i], v);
        }
    }
}

// ---------------------------------------------------------------------------
// 64 blocks x 256 threads. Block g: 256 codes entropy + self-clean, 32 bitset
// words popcount + self-clean; block 0 folds commit/ent warp partials.
// Unique-writer slot partials; ticket-elected last block folds in fixed order.
__global__ void k_reduce(float* __restrict__ out) {
    __shared__ float s_w[8], s_v[8];
    __shared__ float red[256];
    __shared__ int   redi[256];
    int tid  = threadIdx.x;
    int g    = blockIdx.x;
    int lane = tid & 31, wid = tid >> 5;

    int j = g * 256 + tid;
    unsigned long long hv = g_hist[j];
    if (hv) g_hist[j] = 0ull;
    float ae = 0.f;
    if (hv) {
        float avg = (float)((double)hv * (1.0 / FIXSCALE) * (1.0 / 4096.0));
        ae = -avg * __logf(avg + 1e-5f);
    }
    #pragma unroll
    for (int o = 16; o; o >>= 1) ae += __shfl_down_sync(FULLM, ae, o);
    if (lane == 0) s_w[wid] = ae;

    int cnt = 0;
    if (tid < 32) {
        unsigned w = g_bitset[g * 32 + tid];
        if (w) g_bitset[g * 32 + tid] = 0u;
        cnt = __popc(w);
        #pragma unroll
        for (int o = 16; o; o >>= 1) cnt += __shfl_down_sync(FULLM, cnt, o);
    }

    float ce = 0.f;
    if (g == 0) ce = (tid < 128) ? g_wcom[tid] : g_went[tid - 128];
    #pragma unroll
    for (int o = 16; o; o >>= 1) ce += __shfl_down_sync(FULLM, ce, o);
    if (lane == 0) s_v[wid] = ce;

    __syncthreads();
    if (tid == 0) {
        g_pae[g]  = ((s_w[0] + s_w[1]) + (s_w[2] + s_w[3]))
                  + ((s_w[4] + s_w[5]) + (s_w[6] + s_w[7]));
        g_pcnt[g] = cnt;
        if (g == 0) {
            g_pcs = (s_v[0] + s_v[1]) + (s_v[2] + s_v[3]);
            g_pes = (s_v[4] + s_v[5]) + (s_v[6] + s_v[7]);
        }
    }

    __shared__ int s_last;
    __threadfence();
    if (tid == 0) s_last = (atomicAdd(&g_ticket, 1u) == 63u);
    __syncthreads();

    if (s_last) {
        __threadfence();
        red[tid]  = (tid < 64) ? g_pae[tid]  : 0.f;
        redi[tid] = (tid < 64) ? g_pcnt[tid] : 0;
        __syncthreads();
        for (int o = 32; o; o >>= 1) {
            if (tid < o) { red[tid] += red[tid + o]; redi[tid] += redi[tid + o]; }
            __syncthreads();
        }
        if (tid == 0) {
            float avg_e    = red[0];
            float commit   = 0.25f * g_pcs / (float)QELEMS;
            float sample_e = g_pes / (float)N_TOK;
            out[QELEMS + 0] = commit;
            out[QELEMS + 1] = 0.1f * (sample_e - avg_e);
            out[QELEMS + 2] = (float)redi[0] / (float)NE;
            *(volatile unsigned int*)&g_ticket = 0u;   // reset for next replay
        }
    }
}

// ---------------------------------------------------------------------------
extern "C" void kernel_launch(void* const* d_in, const int* in_sizes, int n_in,
                              void* d_out, int out_size) {
    const float* z    = (const float*)d_in[0];
    const int*   used = (const int*)d_in[2];
    float*       out  = (float*)d_out;

    k_main<<<368, 32>>>(z, used, out);
    k_reduce<<<64, 256>>>(out);
}